// round 15
// baseline (speedup 1.0000x reference)
#include <cuda_runtime.h>
#include <cuda_fp16.h>
#include <stdint.h>

#define N_NODES 50000
#define N_EDGES 800000
#define IN_C    128
#define HID_C   128
#define OUT_C   64
#define CAP     64          // ELL capacity per node (P(deg>48) ~ 1e-10)

typedef unsigned long long ull;
union H4 { uint2 u; __half2 h[2]; };
union H8 { uint4 u; __half2 h[4]; };

// ---------------- scratch (static device globals; zero-initialized) ----------
__device__ int    g_cnt [N_NODES];           // ALWAYS zero between calls
__device__ int    g_len [N_NODES];
__device__ int    g_ell [N_NODES * CAP];     // ELL adjacency (by dst)
__device__ float  g_dinv[N_NODES];
__device__ __half g_h1  [N_NODES * HID_C];   // UNSCALED GEMM1 output (fp16)
__device__ __half g_h2  [N_NODES * OUT_C];   // pre-scaled GEMM2 output (fp16)

// ---------------- PTX helpers --------------------------------------------------
__device__ __forceinline__ uint32_t smem_u32(const void* p) {
    uint32_t a;
    asm("{ .reg .u64 t; cvta.to.shared.u64 t, %1; cvt.u32.u64 %0, t; }"
        : "=r"(a) : "l"(p));
    return a;
}

__device__ __forceinline__ void ldsm_x4(uint32_t& r0, uint32_t& r1,
                                        uint32_t& r2, uint32_t& r3, uint32_t addr) {
    asm volatile("ldmatrix.sync.aligned.m8n8.x4.shared.b16 {%0,%1,%2,%3}, [%4];"
                 : "=r"(r0), "=r"(r1), "=r"(r2), "=r"(r3) : "r"(addr));
}

__device__ __forceinline__ void ldsm_x4_t(uint32_t& r0, uint32_t& r1,
                                          uint32_t& r2, uint32_t& r3, uint32_t addr) {
    asm volatile("ldmatrix.sync.aligned.m8n8.x4.trans.shared.b16 {%0,%1,%2,%3}, [%4];"
                 : "=r"(r0), "=r"(r1), "=r"(r2), "=r"(r3) : "r"(addr));
}

__device__ __forceinline__ void mma16816(float* c, const uint32_t* a,
                                         uint32_t b0, uint32_t b1) {
    asm volatile("mma.sync.aligned.m16n8k16.row.col.f32.f16.f16.f32 "
                 "{%0,%1,%2,%3}, {%4,%5,%6,%7}, {%8,%9}, {%0,%1,%2,%3};"
                 : "+f"(c[0]), "+f"(c[1]), "+f"(c[2]), "+f"(c[3])
                 : "r"(a[0]), "r"(a[1]), "r"(a[2]), "r"(a[3]), "r"(b0), "r"(b1));
}

// ---------------- ELL build: count + place in ONE kernel ----------------------
__global__ void k_place_ell(const int* __restrict__ src, const int* __restrict__ dst) {
    int t = blockIdx.x * blockDim.x + threadIdx.x;
    if (t >= N_EDGES / 4) return;
    int4 d4 = reinterpret_cast<const int4*>(dst)[t];
    int4 s4 = reinterpret_cast<const int4*>(src)[t];
    int i0 = atomicAdd(&g_cnt[d4.x], 1);
    int i1 = atomicAdd(&g_cnt[d4.y], 1);
    int i2 = atomicAdd(&g_cnt[d4.z], 1);
    int i3 = atomicAdd(&g_cnt[d4.w], 1);
    if (i0 < CAP) g_ell[d4.x * CAP + i0] = s4.x;
    if (i1 < CAP) g_ell[d4.y * CAP + i1] = s4.y;
    if (i2 < CAP) g_ell[d4.z * CAP + i2] = s4.z;
    if (i3 < CAP) g_ell[d4.w * CAP + i3] = s4.w;
}

__global__ void k_dinv() {
    int i = blockIdx.x * blockDim.x + threadIdx.x;
    if (i >= N_NODES) return;
    int c = g_cnt[i];
    g_len[i]  = (c < CAP) ? c : CAP;
    g_dinv[i] = rsqrtf(1.0f + (float)c);           // +1 self loop
    g_cnt[i]  = 0;                                 // restore zero invariant
}

// ---------------- GEMM1 via mma.sync m16n8k16 (unchanged from R13) ------------
template <int COUT, bool PRESCALE>
__global__ __launch_bounds__(128)
void k_gemm_mma(const float* __restrict__ X, const float* __restrict__ W,
                __half* __restrict__ H)
{
    constexpr int NT   = COUT / 8;
    constexpr int NJP  = NT / 2;
    constexpr int SUBB = 16384;

    extern __shared__ char smem[];
    char* sA = smem;
    char* sW = smem + 2 * SUBB;

    const int tid  = threadIdx.x;
    const int wid  = tid >> 5;
    const int lane = tid & 31;
    const int row0 = blockIdx.x * 128;

    for (int i = tid; i < 128 * 16; i += 128) {
        int r = i >> 4, g = i & 15;
        int gr = row0 + r;
        float4 v0 = make_float4(0.f, 0.f, 0.f, 0.f);
        float4 v1 = v0;
        if (gr < N_NODES) {
            const float4* p = reinterpret_cast<const float4*>(X + (size_t)gr * IN_C + g * 8);
            v0 = p[0]; v1 = p[1];
        }
        H8 h;
        h.h[0] = __floats2half2_rn(v0.x, v0.y);
        h.h[1] = __floats2half2_rn(v0.z, v0.w);
        h.h[2] = __floats2half2_rn(v1.x, v1.y);
        h.h[3] = __floats2half2_rn(v1.z, v1.w);
        int sub = g >> 3, gg = g & 7;
        int off = r * 128 + gg * 16;
        off ^= (off >> 3) & 0x70;
        *reinterpret_cast<uint4*>(sA + sub * SUBB + off) = h.u;
    }
    for (int i = tid; i < 128 * (COUT / 8); i += 128) {
        int r = i / (COUT / 8), g = i % (COUT / 8);
        const float4* p = reinterpret_cast<const float4*>(W + (size_t)r * COUT + g * 8);
        float4 v0 = p[0], v1 = p[1];
        H8 h;
        h.h[0] = __floats2half2_rn(v0.x, v0.y);
        h.h[1] = __floats2half2_rn(v0.z, v0.w);
        h.h[2] = __floats2half2_rn(v1.x, v1.y);
        h.h[3] = __floats2half2_rn(v1.z, v1.w);
        int sub = g >> 3, gg = g & 7;
        int off = r * 128 + gg * 16;
        off ^= (off >> 3) & 0x70;
        *reinterpret_cast<uint4*>(sW + sub * SUBB + off) = h.u;
    }
    __syncthreads();

    const uint32_t sA32 = smem_u32(sA);
    const uint32_t sW32 = smem_u32(sW);

    const int arow = (lane & 7) + ((lane & 8) ? 8 : 0);
    const int cgb  = (lane >> 4) & 1;
    const int xorv = (lane & 7) << 4;

    float acc[2][NT][4];
#pragma unroll
    for (int mt = 0; mt < 2; mt++)
#pragma unroll
        for (int nt = 0; nt < NT; nt++)
#pragma unroll
            for (int q = 0; q < 4; q++) acc[mt][nt][q] = 0.f;

    const int R = wid * 32;

#pragma unroll
    for (int ks = 0; ks < 8; ks++) {
        uint32_t a[2][4];
        const int subA = ks >> 2;
        const int grpA = (ks & 3) * 2 + cgb;
#pragma unroll
        for (int mt = 0; mt < 2; mt++) {
            int off = (R + mt * 16 + arow) * 128 + ((grpA * 16) ^ xorv);
            ldsm_x4(a[mt][0], a[mt][1], a[mt][2], a[mt][3],
                    sA32 + subA * SUBB + off);
        }
#pragma unroll
        for (int jp = 0; jp < NJP; jp++) {
            uint32_t b0, b1, b2, b3;
            const int subB = jp >> 2;
            const int grpB = (jp & 3) * 2 + cgb;
            int off = (ks * 16 + arow) * 128 + ((grpB * 16) ^ xorv);
            ldsm_x4_t(b0, b1, b2, b3, sW32 + subB * SUBB + off);
#pragma unroll
            for (int mt = 0; mt < 2; mt++) {
                mma16816(acc[mt][2 * jp + 0], a[mt], b0, b1);
                mma16816(acc[mt][2 * jp + 1], a[mt], b2, b3);
            }
        }
    }

    const int erow = lane >> 2;
    const int ecol = (lane & 3) * 2;
#pragma unroll
    for (int mt = 0; mt < 2; mt++) {
        int gr0 = row0 + R + mt * 16 + erow;
        int gr1 = gr0 + 8;
        float dv0 = 1.f, dv1 = 1.f;
        if (PRESCALE) {
            if (gr0 < N_NODES) dv0 = g_dinv[gr0];
            if (gr1 < N_NODES) dv1 = g_dinv[gr1];
        }
#pragma unroll
        for (int nt = 0; nt < NT; nt++) {
            if (gr0 < N_NODES) {
                __half2 h = __floats2half2_rn(acc[mt][nt][0] * dv0,
                                              acc[mt][nt][1] * dv0);
                *reinterpret_cast<__half2*>(H + (size_t)gr0 * COUT + nt * 8 + ecol) = h;
            }
            if (gr1 < N_NODES) {
                __half2 h = __floats2half2_rn(acc[mt][nt][2] * dv1,
                                              acc[mt][nt][3] * dv1);
                *reinterpret_cast<__half2*>(H + (size_t)gr1 * COUT + nt * 8 + ecol) = h;
            }
        }
    }
}

// ---------------- FUSED agg1 + GEMM2 (launch_bounds 512,3; unroll 4) ----------
__global__ __launch_bounds__(512, 3)
void k_agg1_gemm2(const float* __restrict__ b1, const float* __restrict__ W2)
{
    constexpr int SUBB = 16384;

    extern __shared__ char smem[];
    char* sX = smem;                    // x2 tile: 2 subtiles (128 x 64h) = 32 KB
    char* sW = smem + 2 * SUBB;         // W2 tile: 1 subtile = 16 KB

    const int tid  = threadIdx.x;
    const int wid  = tid >> 5;          // 0..15
    const int lane = tid & 31;
    const int row0 = blockIdx.x * 128;

    // ---- W2 tile: fp32 -> fp16, swizzled (128 x 64) ----
    for (int i = tid; i < 128 * 8; i += 512) {
        int r = i >> 3, g = i & 7;
        const float4* p = reinterpret_cast<const float4*>(W2 + (size_t)r * OUT_C + g * 8);
        float4 v0 = p[0], v1 = p[1];
        H8 h;
        h.h[0] = __floats2half2_rn(v0.x, v0.y);
        h.h[1] = __floats2half2_rn(v0.z, v0.w);
        h.h[2] = __floats2half2_rn(v1.x, v1.y);
        h.h[3] = __floats2half2_rn(v1.z, v1.w);
        int off = r * 128 + g * 16;
        off ^= (off >> 3) & 0x70;
        *reinterpret_cast<uint4*>(sW + off) = h.u;
    }

    // ---- Phase A: aggregation into smem x2 tile (unroll 4) ----
    const uint2* Hq = reinterpret_cast<const uint2*>(g_h1);
    float4 bv = reinterpret_cast<const float4*>(b1)[lane];

    const int xsub = lane >> 4;
    const int xcol = (8 * lane) & 127;

#define UNPACK4(r, f01, f23) { H4 _t; _t.u = (r); \
        f01 = __half22float2(_t.h[0]); f23 = __half22float2(_t.h[1]); }

#pragma unroll 1
    for (int j = 0; j < 8; j++) {
        const int r  = wid * 8 + j;
        const int n  = row0 + r;
        float4 a0 = make_float4(0.f, 0.f, 0.f, 0.f);
        float4 a1 = a0;
        float dvn = 0.f;

        if (n < N_NODES) {
            dvn = __ldg(&g_dinv[n]);
            {
                uint2 rr = __ldcg(&Hq[(size_t)n * 32 + lane]);
                float2 f01, f23; UNPACK4(rr, f01, f23);
                a0 = make_float4(f01.x * dvn, f01.y * dvn, f23.x * dvn, f23.y * dvn);
            }
            const int len = __ldg(&g_len[n]);
            const int4* E4 = reinterpret_cast<const int4*>(g_ell + n * CAP);
            int f = 0;
            for (; f + 4 <= len; f += 4) {
                int4 ia = __ldg(&E4[f >> 2]);
                float d0 = __ldg(&g_dinv[ia.x]), d1 = __ldg(&g_dinv[ia.y]);
                float d2 = __ldg(&g_dinv[ia.z]), d3 = __ldg(&g_dinv[ia.w]);
                uint2 r0 = __ldcg(&Hq[(size_t)ia.x * 32 + lane]);
                uint2 r1 = __ldcg(&Hq[(size_t)ia.y * 32 + lane]);
                uint2 r2 = __ldcg(&Hq[(size_t)ia.z * 32 + lane]);
                uint2 r3 = __ldcg(&Hq[(size_t)ia.w * 32 + lane]);
                float2 f01, f23;
                UNPACK4(r0, f01, f23);
                a0.x = fmaf(f01.x, d0, a0.x); a0.y = fmaf(f01.y, d0, a0.y);
                a0.z = fmaf(f23.x, d0, a0.z); a0.w = fmaf(f23.y, d0, a0.w);
                UNPACK4(r1, f01, f23);
                a1.x = fmaf(f01.x, d1, a1.x); a1.y = fmaf(f01.y, d1, a1.y);
                a1.z = fmaf(f23.x, d1, a1.z); a1.w = fmaf(f23.y, d1, a1.w);
                UNPACK4(r2, f01, f23);
                a0.x = fmaf(f01.x, d2, a0.x); a0.y = fmaf(f01.y, d2, a0.y);
                a0.z = fmaf(f23.x, d2, a0.z); a0.w = fmaf(f23.y, d2, a0.w);
                UNPACK4(r3, f01, f23);
                a1.x = fmaf(f01.x, d3, a1.x); a1.y = fmaf(f01.y, d3, a1.y);
                a1.z = fmaf(f23.x, d3, a1.z); a1.w = fmaf(f23.y, d3, a1.w);
            }
            for (; f < len; f++) {
                int s = __ldg(&g_ell[n * CAP + f]);
                float d = __ldg(&g_dinv[s]);
                uint2 rr = __ldcg(&Hq[(size_t)s * 32 + lane]);
                float2 f01, f23; UNPACK4(rr, f01, f23);
                a0.x = fmaf(f01.x, d, a0.x); a0.y = fmaf(f01.y, d, a0.y);
                a0.z = fmaf(f23.x, d, a0.z); a0.w = fmaf(f23.y, d, a0.w);
            }
            a0.x += a1.x; a0.y += a1.y; a0.z += a1.z; a0.w += a1.w;
        }

        // relu(dinv*acc + b) -> fp16 -> smem (zeros for OOB rows)
        float ox = 0.f, oy = 0.f, oz = 0.f, ow = 0.f;
        if (n < N_NODES) {
            ox = fmaxf(fmaf(a0.x, dvn, bv.x), 0.f);
            oy = fmaxf(fmaf(a0.y, dvn, bv.y), 0.f);
            oz = fmaxf(fmaf(a0.z, dvn, bv.z), 0.f);
            ow = fmaxf(fmaf(a0.w, dvn, bv.w), 0.f);
        }
        ull pk;
        {
            __half2 h0 = __floats2half2_rn(ox, oy);
            __half2 h1v = __floats2half2_rn(oz, ow);
            uint32_t u0 = *reinterpret_cast<uint32_t*>(&h0);
            uint32_t u1 = *reinterpret_cast<uint32_t*>(&h1v);
            pk = ((ull)u1 << 32) | u0;
        }
        int off = r * 128 + xcol;
        off ^= (off >> 3) & 0x70;
        *reinterpret_cast<ull*>(sX + xsub * SUBB + off) = pk;
    }
    __syncthreads();

    // ---- Phase B: GEMM2 (warps 0-7, 16 rows each, COUT=64) ----
    if (wid < 8) {
        const uint32_t sX32 = smem_u32(sX);
        const uint32_t sW32 = smem_u32(sW);

        const int arow = (lane & 7) + ((lane & 8) ? 8 : 0);
        const int cgb  = (lane >> 4) & 1;
        const int xorv = (lane & 7) << 4;
        const int R = wid * 16;

        float acc[8][4];
#pragma unroll
        for (int nt = 0; nt < 8; nt++)
#pragma unroll
            for (int q = 0; q < 4; q++) acc[nt][q] = 0.f;

#pragma unroll
        for (int ks = 0; ks < 8; ks++) {
            uint32_t a[4];
            const int subA = ks >> 2;
            const int grpA = (ks & 3) * 2 + cgb;
            int offA = (R + arow) * 128 + ((grpA * 16) ^ xorv);
            ldsm_x4(a[0], a[1], a[2], a[3], sX32 + subA * SUBB + offA);
#pragma unroll
            for (int jp = 0; jp < 4; jp++) {
                uint32_t b0, b1, b2, b3;
                const int grpB = jp * 2 + cgb;
                int offB = (ks * 16 + arow) * 128 + ((grpB * 16) ^ xorv);
                ldsm_x4_t(b0, b1, b2, b3, sW32 + offB);
                mma16816(acc[2 * jp + 0], a, b0, b1);
                mma16816(acc[2 * jp + 1], a, b2, b3);
            }
        }

        const int erow = lane >> 2;
        const int ecol = (lane & 3) * 2;
        int gr0 = row0 + R + erow;
        int gr1 = gr0 + 8;
        float dv0 = 1.f, dv1 = 1.f;
        if (gr0 < N_NODES) dv0 = g_dinv[gr0];
        if (gr1 < N_NODES) dv1 = g_dinv[gr1];
#pragma unroll
        for (int nt = 0; nt < 8; nt++) {
            if (gr0 < N_NODES) {
                __half2 h = __floats2half2_rn(acc[nt][0] * dv0, acc[nt][1] * dv0);
                *reinterpret_cast<__half2*>(g_h2 + (size_t)gr0 * OUT_C + nt * 8 + ecol) = h;
            }
            if (gr1 < N_NODES) {
                __half2 h = __floats2half2_rn(acc[nt][2] * dv1, acc[nt][3] * dv1);
                *reinterpret_cast<__half2*>(g_h2 + (size_t)gr1 * OUT_C + nt * 8 + ecol) = h;
            }
        }
    }
}

// ---------------- layer-2 aggregation: half-warp per node, ELL (R10) ----------
__global__ __launch_bounds__(256)
void k_agg2(float* __restrict__ out, const float* __restrict__ b2) {
    int gw   = (blockIdx.x * 256 + threadIdx.x) >> 5;
    int lane = threadIdx.x & 31;
    int n    = gw * 2 + (lane >> 4);
    int hl   = lane & 15;
    if (n >= N_NODES) return;

    const uint2* Hq = reinterpret_cast<const uint2*>(g_h2);

    float4 a0, a1, a2, a3;
    {
        uint2 r = __ldcg(&Hq[(size_t)n * 16 + hl]);
        float2 f01, f23; UNPACK4(r, f01, f23);
        a0 = make_float4(f01.x, f01.y, f23.x, f23.y);   // self (pre-scaled)
    }
    a1 = make_float4(0.f, 0.f, 0.f, 0.f);
    a2 = make_float4(0.f, 0.f, 0.f, 0.f);
    a3 = make_float4(0.f, 0.f, 0.f, 0.f);

    const int len = __ldg(&g_len[n]);
    const int4* E4 = reinterpret_cast<const int4*>(g_ell + n * CAP);
    int f = 0;

    for (; f + 8 <= len; f += 8) {
        int4 ia = __ldg(&E4[(f >> 2) + 0]);
        int4 ib = __ldg(&E4[(f >> 2) + 1]);
        uint2 r0 = __ldcg(&Hq[(size_t)ia.x * 16 + hl]);
        uint2 r1 = __ldcg(&Hq[(size_t)ia.y * 16 + hl]);
        uint2 r2 = __ldcg(&Hq[(size_t)ia.z * 16 + hl]);
        uint2 r3 = __ldcg(&Hq[(size_t)ia.w * 16 + hl]);
        uint2 r4 = __ldcg(&Hq[(size_t)ib.x * 16 + hl]);
        uint2 r5 = __ldcg(&Hq[(size_t)ib.y * 16 + hl]);
        uint2 r6 = __ldcg(&Hq[(size_t)ib.z * 16 + hl]);
        uint2 r7 = __ldcg(&Hq[(size_t)ib.w * 16 + hl]);
        float2 f01, f23;
        UNPACK4(r0, f01, f23);
        a0.x += f01.x; a0.y += f01.y; a0.z += f23.x; a0.w += f23.y;
        UNPACK4(r1, f01, f23);
        a1.x += f01.x; a1.y += f01.y; a1.z += f23.x; a1.w += f23.y;
        UNPACK4(r2, f01, f23);
        a2.x += f01.x; a2.y += f01.y; a2.z += f23.x; a2.w += f23.y;
        UNPACK4(r3, f01, f23);
        a3.x += f01.x; a3.y += f01.y; a3.z += f23.x; a3.w += f23.y;
        UNPACK4(r4, f01, f23);
        a0.x += f01.x; a0.y += f01.y; a0.z += f23.x; a0.w += f23.y;
        UNPACK4(r5, f01, f23);
        a1.x += f01.x; a1.y += f01.y; a1.z += f23.x; a1.w += f23.y;
        UNPACK4(r6, f01, f23);
        a2.x += f01.x; a2.y += f01.y; a2.z += f23.x; a2.w += f23.y;
        UNPACK4(r7, f01, f23);
        a3.x += f01.x; a3.y += f01.y; a3.z += f23.x; a3.w += f23.y;
    }
    for (; f < len; f++) {
        int s = __ldg(&g_ell[n * CAP + f]);
        uint2 r = __ldcg(&Hq[(size_t)s * 16 + hl]);
        float2 f01, f23; UNPACK4(r, f01, f23);
        a0.x += f01.x; a0.y += f01.y; a0.z += f23.x; a0.w += f23.y;
    }
    a0.x += a1.x + a2.x + a3.x;
    a0.y += a1.y + a2.y + a3.y;
    a0.z += a1.z + a2.z + a3.z;
    a0.w += a1.w + a2.w + a3.w;

    float dv = __ldg(&g_dinv[n]);
    float4 b = reinterpret_cast<const float4*>(b2)[hl];
    float4 o;
    o.x = fmaf(a0.x, dv, b.x);
    o.y = fmaf(a0.y, dv, b.y);
    o.z = fmaf(a0.z, dv, b.z);
    o.w = fmaf(a0.w, dv, b.w);
    reinterpret_cast<float4*>(out)[(size_t)n * 16 + hl] = o;
}

// ---------------- launch -------------------------------------------------------
extern "C" void kernel_launch(void* const* d_in, const int* in_sizes, int n_in,
                              void* d_out, int out_size)
{
    const float* x  = (const float*)d_in[0];
    const int*   ei = (const int*)  d_in[1];
    const float* W1 = (const float*)d_in[2];
    const float* b1 = (const float*)d_in[3];
    const float* W2 = (const float*)d_in[4];
    const float* b2 = (const float*)d_in[5];
    float* out = (float*)d_out;

    const int* srcp = ei;             // edge_index[0]
    const int* dstp = ei + N_EDGES;   // edge_index[1]

    __half* h1;
    cudaGetSymbolAddress((void**)&h1, g_h1);

    const int SM1 = 2 * 16384 + 2 * 16384;   // gemm1: A 32KB + W 32KB
    const int SMF = 2 * 16384 + 1 * 16384;   // fused: x2 32KB + W2 16KB

    static cudaStream_t s_aux = nullptr;
    static cudaEvent_t  e_fork = nullptr, e_join = nullptr;
    if (s_aux == nullptr) {
        cudaStreamCreateWithFlags(&s_aux, cudaStreamNonBlocking);
        cudaEventCreateWithFlags(&e_fork, cudaEventDisableTiming);
        cudaEventCreateWithFlags(&e_join, cudaEventDisableTiming);
        cudaFuncSetAttribute(k_gemm_mma<HID_C, false>,
                             cudaFuncAttributeMaxDynamicSharedMemorySize, SM1);
        cudaFuncSetAttribute(k_agg1_gemm2,
                             cudaFuncAttributeMaxDynamicSharedMemorySize, SMF);
    }

    const int tile_blocks = (N_NODES + 127) / 128;   // 391

    // fork point at the start of the call (main stream)
    cudaEventRecord(e_fork, 0);
    cudaStreamWaitEvent(s_aux, e_fork, 0);

    // ---- GEMM1 on aux (no dinv dependency) ----
    k_gemm_mma<HID_C, false><<<tile_blocks, 128, SM1, s_aux>>>(x, W1, h1);
    cudaEventRecord(e_join, s_aux);

    // ---- ELL build on the main stream (overlaps GEMM1) ----
    k_place_ell<<<(N_EDGES / 4 + 255) / 256, 256>>>(srcp, dstp);
    k_dinv     <<<(N_NODES + 255) / 256, 256>>>();

    // ---- join, then FUSED agg1 + GEMM2 ----
    cudaStreamWaitEvent(0, e_join, 0);
    k_agg1_gemm2<<<tile_blocks, 512, SMF>>>(b1, W2);

    // ---- layer-2 aggregation ----
    k_agg2<<<((N_NODES + 1) / 2 * 32 + 255) / 256, 256>>>(out, b2);
}

// round 16
// speedup vs baseline: 1.0386x; 1.0386x over previous
#include <cuda_runtime.h>
#include <cuda_fp16.h>
#include <stdint.h>

#define N_NODES 50000
#define N_EDGES 800000
#define IN_C    128
#define HID_C   128
#define OUT_C   64
#define CAP     64          // ELL capacity per node (P(deg>48) ~ 1e-10)

typedef unsigned long long ull;
union H4 { uint2 u; __half2 h[2]; };
union H8 { uint4 u; __half2 h[4]; };

// ---------------- scratch (static device globals; zero-initialized) ----------
__device__ int    g_cnt [N_NODES];           // ALWAYS zero between calls
__device__ int    g_len [N_NODES];
__device__ int    g_ell [N_NODES * CAP];     // ELL adjacency (by dst)
__device__ float  g_dinv[N_NODES];
__device__ __half g_h1  [N_NODES * HID_C];   // UNSCALED GEMM1 output (fp16)
__device__ __half g_h2  [N_NODES * OUT_C];   // pre-scaled GEMM2 output (fp16)

// ---------------- PTX helpers --------------------------------------------------
__device__ __forceinline__ uint32_t smem_u32(const void* p) {
    uint32_t a;
    asm("{ .reg .u64 t; cvta.to.shared.u64 t, %1; cvt.u32.u64 %0, t; }"
        : "=r"(a) : "l"(p));
    return a;
}

__device__ __forceinline__ void ldsm_x4(uint32_t& r0, uint32_t& r1,
                                        uint32_t& r2, uint32_t& r3, uint32_t addr) {
    asm volatile("ldmatrix.sync.aligned.m8n8.x4.shared.b16 {%0,%1,%2,%3}, [%4];"
                 : "=r"(r0), "=r"(r1), "=r"(r2), "=r"(r3) : "r"(addr));
}

__device__ __forceinline__ void ldsm_x4_t(uint32_t& r0, uint32_t& r1,
                                          uint32_t& r2, uint32_t& r3, uint32_t addr) {
    asm volatile("ldmatrix.sync.aligned.m8n8.x4.trans.shared.b16 {%0,%1,%2,%3}, [%4];"
                 : "=r"(r0), "=r"(r1), "=r"(r2), "=r"(r3) : "r"(addr));
}

__device__ __forceinline__ void mma16816(float* c, const uint32_t* a,
                                         uint32_t b0, uint32_t b1) {
    asm volatile("mma.sync.aligned.m16n8k16.row.col.f32.f16.f16.f32 "
                 "{%0,%1,%2,%3}, {%4,%5,%6,%7}, {%8,%9}, {%0,%1,%2,%3};"
                 : "+f"(c[0]), "+f"(c[1]), "+f"(c[2]), "+f"(c[3])
                 : "r"(a[0]), "r"(a[1]), "r"(a[2]), "r"(a[3]), "r"(b0), "r"(b1));
}

// ---------------- ELL build: count + place in ONE kernel ----------------------
__global__ void k_place_ell(const int* __restrict__ src, const int* __restrict__ dst) {
    int t = blockIdx.x * blockDim.x + threadIdx.x;
    if (t >= N_EDGES / 4) return;
    int4 d4 = reinterpret_cast<const int4*>(dst)[t];
    int4 s4 = reinterpret_cast<const int4*>(src)[t];
    int i0 = atomicAdd(&g_cnt[d4.x], 1);
    int i1 = atomicAdd(&g_cnt[d4.y], 1);
    int i2 = atomicAdd(&g_cnt[d4.z], 1);
    int i3 = atomicAdd(&g_cnt[d4.w], 1);
    if (i0 < CAP) g_ell[d4.x * CAP + i0] = s4.x;
    if (i1 < CAP) g_ell[d4.y * CAP + i1] = s4.y;
    if (i2 < CAP) g_ell[d4.z * CAP + i2] = s4.z;
    if (i3 < CAP) g_ell[d4.w * CAP + i3] = s4.w;
}

__global__ void k_dinv() {
    int i = blockIdx.x * blockDim.x + threadIdx.x;
    if (i >= N_NODES) return;
    int c = g_cnt[i];
    g_len[i]  = (c < CAP) ? c : CAP;
    g_dinv[i] = rsqrtf(1.0f + (float)c);           // +1 self loop
    g_cnt[i]  = 0;                                 // restore zero invariant
}

// ---------------- GEMM1 via mma.sync m16n8k16 (unchanged from R13) ------------
template <int COUT, bool PRESCALE>
__global__ __launch_bounds__(128)
void k_gemm_mma(const float* __restrict__ X, const float* __restrict__ W,
                __half* __restrict__ H)
{
    constexpr int NT   = COUT / 8;
    constexpr int NJP  = NT / 2;
    constexpr int SUBB = 16384;

    extern __shared__ char smem[];
    char* sA = smem;
    char* sW = smem + 2 * SUBB;

    const int tid  = threadIdx.x;
    const int wid  = tid >> 5;
    const int lane = tid & 31;
    const int row0 = blockIdx.x * 128;

    for (int i = tid; i < 128 * 16; i += 128) {
        int r = i >> 4, g = i & 15;
        int gr = row0 + r;
        float4 v0 = make_float4(0.f, 0.f, 0.f, 0.f);
        float4 v1 = v0;
        if (gr < N_NODES) {
            const float4* p = reinterpret_cast<const float4*>(X + (size_t)gr * IN_C + g * 8);
            v0 = p[0]; v1 = p[1];
        }
        H8 h;
        h.h[0] = __floats2half2_rn(v0.x, v0.y);
        h.h[1] = __floats2half2_rn(v0.z, v0.w);
        h.h[2] = __floats2half2_rn(v1.x, v1.y);
        h.h[3] = __floats2half2_rn(v1.z, v1.w);
        int sub = g >> 3, gg = g & 7;
        int off = r * 128 + gg * 16;
        off ^= (off >> 3) & 0x70;
        *reinterpret_cast<uint4*>(sA + sub * SUBB + off) = h.u;
    }
    for (int i = tid; i < 128 * (COUT / 8); i += 128) {
        int r = i / (COUT / 8), g = i % (COUT / 8);
        const float4* p = reinterpret_cast<const float4*>(W + (size_t)r * COUT + g * 8);
        float4 v0 = p[0], v1 = p[1];
        H8 h;
        h.h[0] = __floats2half2_rn(v0.x, v0.y);
        h.h[1] = __floats2half2_rn(v0.z, v0.w);
        h.h[2] = __floats2half2_rn(v1.x, v1.y);
        h.h[3] = __floats2half2_rn(v1.z, v1.w);
        int sub = g >> 3, gg = g & 7;
        int off = r * 128 + gg * 16;
        off ^= (off >> 3) & 0x70;
        *reinterpret_cast<uint4*>(sW + sub * SUBB + off) = h.u;
    }
    __syncthreads();

    const uint32_t sA32 = smem_u32(sA);
    const uint32_t sW32 = smem_u32(sW);

    const int arow = (lane & 7) + ((lane & 8) ? 8 : 0);
    const int cgb  = (lane >> 4) & 1;
    const int xorv = (lane & 7) << 4;

    float acc[2][NT][4];
#pragma unroll
    for (int mt = 0; mt < 2; mt++)
#pragma unroll
        for (int nt = 0; nt < NT; nt++)
#pragma unroll
            for (int q = 0; q < 4; q++) acc[mt][nt][q] = 0.f;

    const int R = wid * 32;

#pragma unroll
    for (int ks = 0; ks < 8; ks++) {
        uint32_t a[2][4];
        const int subA = ks >> 2;
        const int grpA = (ks & 3) * 2 + cgb;
#pragma unroll
        for (int mt = 0; mt < 2; mt++) {
            int off = (R + mt * 16 + arow) * 128 + ((grpA * 16) ^ xorv);
            ldsm_x4(a[mt][0], a[mt][1], a[mt][2], a[mt][3],
                    sA32 + subA * SUBB + off);
        }
#pragma unroll
        for (int jp = 0; jp < NJP; jp++) {
            uint32_t b0, b1, b2, b3;
            const int subB = jp >> 2;
            const int grpB = (jp & 3) * 2 + cgb;
            int off = (ks * 16 + arow) * 128 + ((grpB * 16) ^ xorv);
            ldsm_x4_t(b0, b1, b2, b3, sW32 + subB * SUBB + off);
#pragma unroll
            for (int mt = 0; mt < 2; mt++) {
                mma16816(acc[mt][2 * jp + 0], a[mt], b0, b1);
                mma16816(acc[mt][2 * jp + 1], a[mt], b2, b3);
            }
        }
    }

    const int erow = lane >> 2;
    const int ecol = (lane & 3) * 2;
#pragma unroll
    for (int mt = 0; mt < 2; mt++) {
        int gr0 = row0 + R + mt * 16 + erow;
        int gr1 = gr0 + 8;
        float dv0 = 1.f, dv1 = 1.f;
        if (PRESCALE) {
            if (gr0 < N_NODES) dv0 = g_dinv[gr0];
            if (gr1 < N_NODES) dv1 = g_dinv[gr1];
        }
#pragma unroll
        for (int nt = 0; nt < NT; nt++) {
            if (gr0 < N_NODES) {
                __half2 h = __floats2half2_rn(acc[mt][nt][0] * dv0,
                                              acc[mt][nt][1] * dv0);
                *reinterpret_cast<__half2*>(H + (size_t)gr0 * COUT + nt * 8 + ecol) = h;
            }
            if (gr1 < N_NODES) {
                __half2 h = __floats2half2_rn(acc[mt][nt][2] * dv1,
                                              acc[mt][nt][3] * dv1);
                *reinterpret_cast<__half2*>(H + (size_t)gr1 * COUT + nt * 8 + ecol) = h;
            }
        }
    }
}

// ---------------- FUSED agg1 + GEMM2 (lb 512,3; pipelined index loads) --------
__global__ __launch_bounds__(512, 3)
void k_agg1_gemm2(const float* __restrict__ b1, const float* __restrict__ W2)
{
    constexpr int SUBB = 16384;

    extern __shared__ char smem[];
    char* sX = smem;                    // x2 tile: 2 subtiles (128 x 64h) = 32 KB
    char* sW = smem + 2 * SUBB;         // W2 tile: 1 subtile = 16 KB

    const int tid  = threadIdx.x;
    const int wid  = tid >> 5;          // 0..15
    const int lane = tid & 31;
    const int row0 = blockIdx.x * 128;

    // ---- W2 tile: fp32 -> fp16, swizzled (128 x 64) ----
    for (int i = tid; i < 128 * 8; i += 512) {
        int r = i >> 3, g = i & 7;
        const float4* p = reinterpret_cast<const float4*>(W2 + (size_t)r * OUT_C + g * 8);
        float4 v0 = p[0], v1 = p[1];
        H8 h;
        h.h[0] = __floats2half2_rn(v0.x, v0.y);
        h.h[1] = __floats2half2_rn(v0.z, v0.w);
        h.h[2] = __floats2half2_rn(v1.x, v1.y);
        h.h[3] = __floats2half2_rn(v1.z, v1.w);
        int off = r * 128 + g * 16;
        off ^= (off >> 3) & 0x70;
        *reinterpret_cast<uint4*>(sW + off) = h.u;
    }

    // ---- Phase A: aggregation into smem x2 tile (unroll 4, pipelined idx) ----
    const uint2* Hq = reinterpret_cast<const uint2*>(g_h1);
    float4 bv = reinterpret_cast<const float4*>(b1)[lane];

    const int xsub = lane >> 4;
    const int xcol = (8 * lane) & 127;

#define UNPACK4(r, f01, f23) { H4 _t; _t.u = (r); \
        f01 = __half22float2(_t.h[0]); f23 = __half22float2(_t.h[1]); }

#pragma unroll 1
    for (int j = 0; j < 8; j++) {
        const int r  = wid * 8 + j;
        const int n  = row0 + r;
        float4 a0 = make_float4(0.f, 0.f, 0.f, 0.f);
        float4 a1 = a0;
        float dvn = 0.f;

        if (n < N_NODES) {
            dvn = __ldg(&g_dinv[n]);
            {
                uint2 rr = __ldcg(&Hq[(size_t)n * 32 + lane]);
                float2 f01, f23; UNPACK4(rr, f01, f23);
                a0 = make_float4(f01.x * dvn, f01.y * dvn, f23.x * dvn, f23.y * dvn);
            }
            const int len = __ldg(&g_len[n]);
            const int4* E4 = reinterpret_cast<const int4*>(g_ell + n * CAP);
            const int nfull = len >> 2;              // full int4 groups

            if (nfull > 0) {
                int4 ia = __ldg(&E4[0]);             // prologue index load
#pragma unroll 1
                for (int q = 0; q < nfull; q++) {
                    int4 cur = ia;
                    if (q + 1 < nfull) ia = __ldg(&E4[q + 1]);   // pipelined next
                    float d0 = __ldg(&g_dinv[cur.x]), d1 = __ldg(&g_dinv[cur.y]);
                    float d2 = __ldg(&g_dinv[cur.z]), d3 = __ldg(&g_dinv[cur.w]);
                    uint2 r0 = __ldcg(&Hq[(size_t)cur.x * 32 + lane]);
                    uint2 r1 = __ldcg(&Hq[(size_t)cur.y * 32 + lane]);
                    uint2 r2 = __ldcg(&Hq[(size_t)cur.z * 32 + lane]);
                    uint2 r3 = __ldcg(&Hq[(size_t)cur.w * 32 + lane]);
                    float2 f01, f23;
                    UNPACK4(r0, f01, f23);
                    a0.x = fmaf(f01.x, d0, a0.x); a0.y = fmaf(f01.y, d0, a0.y);
                    a0.z = fmaf(f23.x, d0, a0.z); a0.w = fmaf(f23.y, d0, a0.w);
                    UNPACK4(r1, f01, f23);
                    a1.x = fmaf(f01.x, d1, a1.x); a1.y = fmaf(f01.y, d1, a1.y);
                    a1.z = fmaf(f23.x, d1, a1.z); a1.w = fmaf(f23.y, d1, a1.w);
                    UNPACK4(r2, f01, f23);
                    a0.x = fmaf(f01.x, d2, a0.x); a0.y = fmaf(f01.y, d2, a0.y);
                    a0.z = fmaf(f23.x, d2, a0.z); a0.w = fmaf(f23.y, d2, a0.w);
                    UNPACK4(r3, f01, f23);
                    a1.x = fmaf(f01.x, d3, a1.x); a1.y = fmaf(f01.y, d3, a1.y);
                    a1.z = fmaf(f23.x, d3, a1.z); a1.w = fmaf(f23.y, d3, a1.w);
                }
            }
            for (int f = nfull << 2; f < len; f++) {
                int s = __ldg(&g_ell[n * CAP + f]);
                float d = __ldg(&g_dinv[s]);
                uint2 rr = __ldcg(&Hq[(size_t)s * 32 + lane]);
                float2 f01, f23; UNPACK4(rr, f01, f23);
                a0.x = fmaf(f01.x, d, a0.x); a0.y = fmaf(f01.y, d, a0.y);
                a0.z = fmaf(f23.x, d, a0.z); a0.w = fmaf(f23.y, d, a0.w);
            }
            a0.x += a1.x; a0.y += a1.y; a0.z += a1.z; a0.w += a1.w;
        }

        // relu(dinv*acc + b) -> fp16 -> smem (zeros for OOB rows)
        float ox = 0.f, oy = 0.f, oz = 0.f, ow = 0.f;
        if (n < N_NODES) {
            ox = fmaxf(fmaf(a0.x, dvn, bv.x), 0.f);
            oy = fmaxf(fmaf(a0.y, dvn, bv.y), 0.f);
            oz = fmaxf(fmaf(a0.z, dvn, bv.z), 0.f);
            ow = fmaxf(fmaf(a0.w, dvn, bv.w), 0.f);
        }
        ull pk;
        {
            __half2 h0 = __floats2half2_rn(ox, oy);
            __half2 h1v = __floats2half2_rn(oz, ow);
            uint32_t u0 = *reinterpret_cast<uint32_t*>(&h0);
            uint32_t u1 = *reinterpret_cast<uint32_t*>(&h1v);
            pk = ((ull)u1 << 32) | u0;
        }
        int off = r * 128 + xcol;
        off ^= (off >> 3) & 0x70;
        *reinterpret_cast<ull*>(sX + xsub * SUBB + off) = pk;
    }
    __syncthreads();

    // ---- Phase B: GEMM2 (warps 0-7, 16 rows each, COUT=64) ----
    if (wid < 8) {
        const uint32_t sX32 = smem_u32(sX);
        const uint32_t sW32 = smem_u32(sW);

        const int arow = (lane & 7) + ((lane & 8) ? 8 : 0);
        const int cgb  = (lane >> 4) & 1;
        const int xorv = (lane & 7) << 4;
        const int R = wid * 16;

        float acc[8][4];
#pragma unroll
        for (int nt = 0; nt < 8; nt++)
#pragma unroll
            for (int q = 0; q < 4; q++) acc[nt][q] = 0.f;

#pragma unroll
        for (int ks = 0; ks < 8; ks++) {
            uint32_t a[4];
            const int subA = ks >> 2;
            const int grpA = (ks & 3) * 2 + cgb;
            int offA = (R + arow) * 128 + ((grpA * 16) ^ xorv);
            ldsm_x4(a[0], a[1], a[2], a[3], sX32 + subA * SUBB + offA);
#pragma unroll
            for (int jp = 0; jp < 4; jp++) {
                uint32_t b0, b1, b2, b3;
                const int grpB = jp * 2 + cgb;
                int offB = (ks * 16 + arow) * 128 + ((grpB * 16) ^ xorv);
                ldsm_x4_t(b0, b1, b2, b3, sW32 + offB);
                mma16816(acc[2 * jp + 0], a, b0, b1);
                mma16816(acc[2 * jp + 1], a, b2, b3);
            }
        }

        const int erow = lane >> 2;
        const int ecol = (lane & 3) * 2;
        int gr0 = row0 + R + erow;
        int gr1 = gr0 + 8;
        float dv0 = 1.f, dv1 = 1.f;
        if (gr0 < N_NODES) dv0 = g_dinv[gr0];
        if (gr1 < N_NODES) dv1 = g_dinv[gr1];
#pragma unroll
        for (int nt = 0; nt < 8; nt++) {
            if (gr0 < N_NODES) {
                __half2 h = __floats2half2_rn(acc[nt][0] * dv0, acc[nt][1] * dv0);
                *reinterpret_cast<__half2*>(g_h2 + (size_t)gr0 * OUT_C + nt * 8 + ecol) = h;
            }
            if (gr1 < N_NODES) {
                __half2 h = __floats2half2_rn(acc[nt][2] * dv1, acc[nt][3] * dv1);
                *reinterpret_cast<__half2*>(g_h2 + (size_t)gr1 * OUT_C + nt * 8 + ecol) = h;
            }
        }
    }
}

// ---------------- layer-2 aggregation: half-warp per node, pipelined idx ------
__global__ __launch_bounds__(256)
void k_agg2(float* __restrict__ out, const float* __restrict__ b2) {
    int gw   = (blockIdx.x * 256 + threadIdx.x) >> 5;
    int lane = threadIdx.x & 31;
    int n    = gw * 2 + (lane >> 4);
    int hl   = lane & 15;
    if (n >= N_NODES) return;

    const uint2* Hq = reinterpret_cast<const uint2*>(g_h2);

    float4 a0, a1;
    {
        uint2 r = __ldcg(&Hq[(size_t)n * 16 + hl]);
        float2 f01, f23; UNPACK4(r, f01, f23);
        a0 = make_float4(f01.x, f01.y, f23.x, f23.y);   // self (pre-scaled)
    }
    a1 = make_float4(0.f, 0.f, 0.f, 0.f);

    const int len = __ldg(&g_len[n]);
    const int4* E4 = reinterpret_cast<const int4*>(g_ell + n * CAP);
    const int nfull = len >> 2;

    if (nfull > 0) {
        int4 ia = __ldg(&E4[0]);
#pragma unroll 1
        for (int q = 0; q < nfull; q++) {
            int4 cur = ia;
            if (q + 1 < nfull) ia = __ldg(&E4[q + 1]);
            uint2 r0 = __ldcg(&Hq[(size_t)cur.x * 16 + hl]);
            uint2 r1 = __ldcg(&Hq[(size_t)cur.y * 16 + hl]);
            uint2 r2 = __ldcg(&Hq[(size_t)cur.z * 16 + hl]);
            uint2 r3 = __ldcg(&Hq[(size_t)cur.w * 16 + hl]);
            float2 f01, f23;
            UNPACK4(r0, f01, f23);
            a0.x += f01.x; a0.y += f01.y; a0.z += f23.x; a0.w += f23.y;
            UNPACK4(r1, f01, f23);
            a1.x += f01.x; a1.y += f01.y; a1.z += f23.x; a1.w += f23.y;
            UNPACK4(r2, f01, f23);
            a0.x += f01.x; a0.y += f01.y; a0.z += f23.x; a0.w += f23.y;
            UNPACK4(r3, f01, f23);
            a1.x += f01.x; a1.y += f01.y; a1.z += f23.x; a1.w += f23.y;
        }
    }
    for (int f = nfull << 2; f < len; f++) {
        int s = __ldg(&g_ell[n * CAP + f]);
        uint2 r = __ldcg(&Hq[(size_t)s * 16 + hl]);
        float2 f01, f23; UNPACK4(r, f01, f23);
        a0.x += f01.x; a0.y += f01.y; a0.z += f23.x; a0.w += f23.y;
    }
    a0.x += a1.x; a0.y += a1.y; a0.z += a1.z; a0.w += a1.w;

    float dv = __ldg(&g_dinv[n]);
    float4 b = reinterpret_cast<const float4*>(b2)[hl];
    float4 o;
    o.x = fmaf(a0.x, dv, b.x);
    o.y = fmaf(a0.y, dv, b.y);
    o.z = fmaf(a0.z, dv, b.z);
    o.w = fmaf(a0.w, dv, b.w);
    reinterpret_cast<float4*>(out)[(size_t)n * 16 + hl] = o;
}

// ---------------- launch -------------------------------------------------------
extern "C" void kernel_launch(void* const* d_in, const int* in_sizes, int n_in,
                              void* d_out, int out_size)
{
    const float* x  = (const float*)d_in[0];
    const int*   ei = (const int*)  d_in[1];
    const float* W1 = (const float*)d_in[2];
    const float* b1 = (const float*)d_in[3];
    const float* W2 = (const float*)d_in[4];
    const float* b2 = (const float*)d_in[5];
    float* out = (float*)d_out;

    const int* srcp = ei;             // edge_index[0]
    const int* dstp = ei + N_EDGES;   // edge_index[1]

    __half* h1;
    cudaGetSymbolAddress((void**)&h1, g_h1);

    const int SM1 = 2 * 16384 + 2 * 16384;   // gemm1: A 32KB + W 32KB
    const int SMF = 2 * 16384 + 1 * 16384;   // fused: x2 32KB + W2 16KB

    static cudaStream_t s_aux = nullptr;
    static cudaEvent_t  e_fork = nullptr, e_join = nullptr;
    if (s_aux == nullptr) {
        cudaStreamCreateWithFlags(&s_aux, cudaStreamNonBlocking);
        cudaEventCreateWithFlags(&e_fork, cudaEventDisableTiming);
        cudaEventCreateWithFlags(&e_join, cudaEventDisableTiming);
        cudaFuncSetAttribute(k_gemm_mma<HID_C, false>,
                             cudaFuncAttributeMaxDynamicSharedMemorySize, SM1);
        cudaFuncSetAttribute(k_agg1_gemm2,
                             cudaFuncAttributeMaxDynamicSharedMemorySize, SMF);
    }

    const int tile_blocks = (N_NODES + 127) / 128;   // 391

    // fork point at the start of the call (main stream)
    cudaEventRecord(e_fork, 0);
    cudaStreamWaitEvent(s_aux, e_fork, 0);

    // ---- GEMM1 on aux (no dinv dependency) ----
    k_gemm_mma<HID_C, false><<<tile_blocks, 128, SM1, s_aux>>>(x, W1, h1);
    cudaEventRecord(e_join, s_aux);

    // ---- ELL build on the main stream (overlaps GEMM1) ----
    k_place_ell<<<(N_EDGES / 4 + 255) / 256, 256>>>(srcp, dstp);
    k_dinv     <<<(N_NODES + 255) / 256, 256>>>();

    // ---- join, then FUSED agg1 + GEMM2 ----
    cudaStreamWaitEvent(0, e_join, 0);
    k_agg1_gemm2<<<tile_blocks, 512, SMF>>>(b1, W2);

    // ---- layer-2 aggregation ----
    k_agg2<<<((N_NODES + 1) / 2 * 32 + 255) / 256, 256>>>(out, b2);
}

// round 17
// speedup vs baseline: 1.0795x; 1.0394x over previous
#include <cuda_runtime.h>
#include <cuda_fp16.h>
#include <stdint.h>

#define N_NODES 50000
#define N_EDGES 800000
#define IN_C    128
#define HID_C   128
#define OUT_C   64
#define CAP     64          // ELL capacity per node (P(deg>48) ~ 1e-10)

typedef unsigned long long ull;
union H4 { uint2 u; __half2 h[2]; };
union H8 { uint4 u; __half2 h[4]; };

// ---------------- scratch (static device globals; zero-initialized) ----------
__device__ int    g_cnt [N_NODES];           // ALWAYS zero between calls
__device__ int    g_len [N_NODES];
__device__ int    g_ell [N_NODES * CAP];     // ELL adjacency (by dst)
__device__ float  g_dinv[N_NODES];
__device__ __half g_h1  [N_NODES * HID_C];   // UNSCALED GEMM1 output (fp16)
__device__ __half g_h2  [N_NODES * OUT_C];   // pre-scaled GEMM2 output (fp16)

// ---------------- PTX helpers --------------------------------------------------
__device__ __forceinline__ uint32_t smem_u32(const void* p) {
    uint32_t a;
    asm("{ .reg .u64 t; cvta.to.shared.u64 t, %1; cvt.u32.u64 %0, t; }"
        : "=r"(a) : "l"(p));
    return a;
}

__device__ __forceinline__ void ldsm_x4(uint32_t& r0, uint32_t& r1,
                                        uint32_t& r2, uint32_t& r3, uint32_t addr) {
    asm volatile("ldmatrix.sync.aligned.m8n8.x4.shared.b16 {%0,%1,%2,%3}, [%4];"
                 : "=r"(r0), "=r"(r1), "=r"(r2), "=r"(r3) : "r"(addr));
}

__device__ __forceinline__ void ldsm_x4_t(uint32_t& r0, uint32_t& r1,
                                          uint32_t& r2, uint32_t& r3, uint32_t addr) {
    asm volatile("ldmatrix.sync.aligned.m8n8.x4.trans.shared.b16 {%0,%1,%2,%3}, [%4];"
                 : "=r"(r0), "=r"(r1), "=r"(r2), "=r"(r3) : "r"(addr));
}

__device__ __forceinline__ void mma16816(float* c, const uint32_t* a,
                                         uint32_t b0, uint32_t b1) {
    asm volatile("mma.sync.aligned.m16n8k16.row.col.f32.f16.f16.f32 "
                 "{%0,%1,%2,%3}, {%4,%5,%6,%7}, {%8,%9}, {%0,%1,%2,%3};"
                 : "+f"(c[0]), "+f"(c[1]), "+f"(c[2]), "+f"(c[3])
                 : "r"(a[0]), "r"(a[1]), "r"(a[2]), "r"(a[3]), "r"(b0), "r"(b1));
}

// ---------------- ELL build: count + place over a quad range ------------------
__global__ void k_place_ell(const int* __restrict__ src, const int* __restrict__ dst,
                            int q0, int q1) {
    int t = q0 + blockIdx.x * blockDim.x + threadIdx.x;
    if (t >= q1) return;
    int4 d4 = reinterpret_cast<const int4*>(dst)[t];
    int4 s4 = reinterpret_cast<const int4*>(src)[t];
    int i0 = atomicAdd(&g_cnt[d4.x], 1);
    int i1 = atomicAdd(&g_cnt[d4.y], 1);
    int i2 = atomicAdd(&g_cnt[d4.z], 1);
    int i3 = atomicAdd(&g_cnt[d4.w], 1);
    if (i0 < CAP) g_ell[d4.x * CAP + i0] = s4.x;
    if (i1 < CAP) g_ell[d4.y * CAP + i1] = s4.y;
    if (i2 < CAP) g_ell[d4.z * CAP + i2] = s4.z;
    if (i3 < CAP) g_ell[d4.w * CAP + i3] = s4.w;
}

__global__ void k_dinv() {
    int i = blockIdx.x * blockDim.x + threadIdx.x;
    if (i >= N_NODES) return;
    int c = g_cnt[i];
    g_len[i]  = (c < CAP) ? c : CAP;
    g_dinv[i] = rsqrtf(1.0f + (float)c);           // +1 self loop
    g_cnt[i]  = 0;                                 // restore zero invariant
}

// ---------------- GEMM1 via mma.sync m16n8k16 (unchanged from R13) ------------
template <int COUT, bool PRESCALE>
__global__ __launch_bounds__(128)
void k_gemm_mma(const float* __restrict__ X, const float* __restrict__ W,
                __half* __restrict__ H)
{
    constexpr int NT   = COUT / 8;
    constexpr int NJP  = NT / 2;
    constexpr int SUBB = 16384;

    extern __shared__ char smem[];
    char* sA = smem;
    char* sW = smem + 2 * SUBB;

    const int tid  = threadIdx.x;
    const int wid  = tid >> 5;
    const int lane = tid & 31;
    const int row0 = blockIdx.x * 128;

    for (int i = tid; i < 128 * 16; i += 128) {
        int r = i >> 4, g = i & 15;
        int gr = row0 + r;
        float4 v0 = make_float4(0.f, 0.f, 0.f, 0.f);
        float4 v1 = v0;
        if (gr < N_NODES) {
            const float4* p = reinterpret_cast<const float4*>(X + (size_t)gr * IN_C + g * 8);
            v0 = p[0]; v1 = p[1];
        }
        H8 h;
        h.h[0] = __floats2half2_rn(v0.x, v0.y);
        h.h[1] = __floats2half2_rn(v0.z, v0.w);
        h.h[2] = __floats2half2_rn(v1.x, v1.y);
        h.h[3] = __floats2half2_rn(v1.z, v1.w);
        int sub = g >> 3, gg = g & 7;
        int off = r * 128 + gg * 16;
        off ^= (off >> 3) & 0x70;
        *reinterpret_cast<uint4*>(sA + sub * SUBB + off) = h.u;
    }
    for (int i = tid; i < 128 * (COUT / 8); i += 128) {
        int r = i / (COUT / 8), g = i % (COUT / 8);
        const float4* p = reinterpret_cast<const float4*>(W + (size_t)r * COUT + g * 8);
        float4 v0 = p[0], v1 = p[1];
        H8 h;
        h.h[0] = __floats2half2_rn(v0.x, v0.y);
        h.h[1] = __floats2half2_rn(v0.z, v0.w);
        h.h[2] = __floats2half2_rn(v1.x, v1.y);
        h.h[3] = __floats2half2_rn(v1.z, v1.w);
        int sub = g >> 3, gg = g & 7;
        int off = r * 128 + gg * 16;
        off ^= (off >> 3) & 0x70;
        *reinterpret_cast<uint4*>(sW + sub * SUBB + off) = h.u;
    }
    __syncthreads();

    const uint32_t sA32 = smem_u32(sA);
    const uint32_t sW32 = smem_u32(sW);

    const int arow = (lane & 7) + ((lane & 8) ? 8 : 0);
    const int cgb  = (lane >> 4) & 1;
    const int xorv = (lane & 7) << 4;

    float acc[2][NT][4];
#pragma unroll
    for (int mt = 0; mt < 2; mt++)
#pragma unroll
        for (int nt = 0; nt < NT; nt++)
#pragma unroll
            for (int q = 0; q < 4; q++) acc[mt][nt][q] = 0.f;

    const int R = wid * 32;

#pragma unroll
    for (int ks = 0; ks < 8; ks++) {
        uint32_t a[2][4];
        const int subA = ks >> 2;
        const int grpA = (ks & 3) * 2 + cgb;
#pragma unroll
        for (int mt = 0; mt < 2; mt++) {
            int off = (R + mt * 16 + arow) * 128 + ((grpA * 16) ^ xorv);
            ldsm_x4(a[mt][0], a[mt][1], a[mt][2], a[mt][3],
                    sA32 + subA * SUBB + off);
        }
#pragma unroll
        for (int jp = 0; jp < NJP; jp++) {
            uint32_t b0, b1, b2, b3;
            const int subB = jp >> 2;
            const int grpB = (jp & 3) * 2 + cgb;
            int off = (ks * 16 + arow) * 128 + ((grpB * 16) ^ xorv);
            ldsm_x4_t(b0, b1, b2, b3, sW32 + subB * SUBB + off);
#pragma unroll
            for (int mt = 0; mt < 2; mt++) {
                mma16816(acc[mt][2 * jp + 0], a[mt], b0, b1);
                mma16816(acc[mt][2 * jp + 1], a[mt], b2, b3);
            }
        }
    }

    const int erow = lane >> 2;
    const int ecol = (lane & 3) * 2;
#pragma unroll
    for (int mt = 0; mt < 2; mt++) {
        int gr0 = row0 + R + mt * 16 + erow;
        int gr1 = gr0 + 8;
        float dv0 = 1.f, dv1 = 1.f;
        if (PRESCALE) {
            if (gr0 < N_NODES) dv0 = g_dinv[gr0];
            if (gr1 < N_NODES) dv1 = g_dinv[gr1];
        }
#pragma unroll
        for (int nt = 0; nt < NT; nt++) {
            if (gr0 < N_NODES) {
                __half2 h = __floats2half2_rn(acc[mt][nt][0] * dv0,
                                              acc[mt][nt][1] * dv0);
                *reinterpret_cast<__half2*>(H + (size_t)gr0 * COUT + nt * 8 + ecol) = h;
            }
            if (gr1 < N_NODES) {
                __half2 h = __floats2half2_rn(acc[mt][nt][2] * dv1,
                                              acc[mt][nt][3] * dv1);
                *reinterpret_cast<__half2*>(H + (size_t)gr1 * COUT + nt * 8 + ecol) = h;
            }
        }
    }
}

// ---------------- FUSED agg1 + GEMM2 (lb 512,3; 16-warp Phase B) --------------
__global__ __launch_bounds__(512, 3)
void k_agg1_gemm2(const float* __restrict__ b1, const float* __restrict__ W2)
{
    constexpr int SUBB = 16384;

    extern __shared__ char smem[];
    char* sX = smem;                    // x2 tile: 2 subtiles (128 x 64h) = 32 KB
    char* sW = smem + 2 * SUBB;         // W2 tile: 1 subtile = 16 KB

    const int tid  = threadIdx.x;
    const int wid  = tid >> 5;          // 0..15
    const int lane = tid & 31;
    const int row0 = blockIdx.x * 128;

    // ---- W2 tile: fp32 -> fp16, swizzled (128 x 64) ----
    for (int i = tid; i < 128 * 8; i += 512) {
        int r = i >> 3, g = i & 7;
        const float4* p = reinterpret_cast<const float4*>(W2 + (size_t)r * OUT_C + g * 8);
        float4 v0 = p[0], v1 = p[1];
        H8 h;
        h.h[0] = __floats2half2_rn(v0.x, v0.y);
        h.h[1] = __floats2half2_rn(v0.z, v0.w);
        h.h[2] = __floats2half2_rn(v1.x, v1.y);
        h.h[3] = __floats2half2_rn(v1.z, v1.w);
        int off = r * 128 + g * 16;
        off ^= (off >> 3) & 0x70;
        *reinterpret_cast<uint4*>(sW + off) = h.u;
    }

    // ---- Phase A: aggregation into smem x2 tile (unroll 4, pipelined idx) ----
    const uint2* Hq = reinterpret_cast<const uint2*>(g_h1);
    float4 bv = reinterpret_cast<const float4*>(b1)[lane];

    const int xsub = lane >> 4;
    const int xcol = (8 * lane) & 127;

#define UNPACK4(r, f01, f23) { H4 _t; _t.u = (r); \
        f01 = __half22float2(_t.h[0]); f23 = __half22float2(_t.h[1]); }

#pragma unroll 1
    for (int j = 0; j < 8; j++) {
        const int r  = wid * 8 + j;
        const int n  = row0 + r;
        float4 a0 = make_float4(0.f, 0.f, 0.f, 0.f);
        float4 a1 = a0;
        float dvn = 0.f;

        if (n < N_NODES) {
            dvn = __ldg(&g_dinv[n]);
            {
                uint2 rr = __ldcg(&Hq[(size_t)n * 32 + lane]);
                float2 f01, f23; UNPACK4(rr, f01, f23);
                a0 = make_float4(f01.x * dvn, f01.y * dvn, f23.x * dvn, f23.y * dvn);
            }
            const int len = __ldg(&g_len[n]);
            const int4* E4 = reinterpret_cast<const int4*>(g_ell + n * CAP);
            const int nfull = len >> 2;              // full int4 groups

            if (nfull > 0) {
                int4 ia = __ldg(&E4[0]);             // prologue index load
#pragma unroll 1
                for (int q = 0; q < nfull; q++) {
                    int4 cur = ia;
                    if (q + 1 < nfull) ia = __ldg(&E4[q + 1]);   // pipelined next
                    float d0 = __ldg(&g_dinv[cur.x]), d1 = __ldg(&g_dinv[cur.y]);
                    float d2 = __ldg(&g_dinv[cur.z]), d3 = __ldg(&g_dinv[cur.w]);
                    uint2 r0 = __ldcg(&Hq[(size_t)cur.x * 32 + lane]);
                    uint2 r1 = __ldcg(&Hq[(size_t)cur.y * 32 + lane]);
                    uint2 r2 = __ldcg(&Hq[(size_t)cur.z * 32 + lane]);
                    uint2 r3 = __ldcg(&Hq[(size_t)cur.w * 32 + lane]);
                    float2 f01, f23;
                    UNPACK4(r0, f01, f23);
                    a0.x = fmaf(f01.x, d0, a0.x); a0.y = fmaf(f01.y, d0, a0.y);
                    a0.z = fmaf(f23.x, d0, a0.z); a0.w = fmaf(f23.y, d0, a0.w);
                    UNPACK4(r1, f01, f23);
                    a1.x = fmaf(f01.x, d1, a1.x); a1.y = fmaf(f01.y, d1, a1.y);
                    a1.z = fmaf(f23.x, d1, a1.z); a1.w = fmaf(f23.y, d1, a1.w);
                    UNPACK4(r2, f01, f23);
                    a0.x = fmaf(f01.x, d2, a0.x); a0.y = fmaf(f01.y, d2, a0.y);
                    a0.z = fmaf(f23.x, d2, a0.z); a0.w = fmaf(f23.y, d2, a0.w);
                    UNPACK4(r3, f01, f23);
                    a1.x = fmaf(f01.x, d3, a1.x); a1.y = fmaf(f01.y, d3, a1.y);
                    a1.z = fmaf(f23.x, d3, a1.z); a1.w = fmaf(f23.y, d3, a1.w);
                }
            }
            for (int f = nfull << 2; f < len; f++) {
                int s = __ldg(&g_ell[n * CAP + f]);
                float d = __ldg(&g_dinv[s]);
                uint2 rr = __ldcg(&Hq[(size_t)s * 32 + lane]);
                float2 f01, f23; UNPACK4(rr, f01, f23);
                a0.x = fmaf(f01.x, d, a0.x); a0.y = fmaf(f01.y, d, a0.y);
                a0.z = fmaf(f23.x, d, a0.z); a0.w = fmaf(f23.y, d, a0.w);
            }
            a0.x += a1.x; a0.y += a1.y; a0.z += a1.z; a0.w += a1.w;
        }

        // relu(dinv*acc + b) -> fp16 -> smem (zeros for OOB rows)
        float ox = 0.f, oy = 0.f, oz = 0.f, ow = 0.f;
        if (n < N_NODES) {
            ox = fmaxf(fmaf(a0.x, dvn, bv.x), 0.f);
            oy = fmaxf(fmaf(a0.y, dvn, bv.y), 0.f);
            oz = fmaxf(fmaf(a0.z, dvn, bv.z), 0.f);
            ow = fmaxf(fmaf(a0.w, dvn, bv.w), 0.f);
        }
        ull pk;
        {
            __half2 h0 = __floats2half2_rn(ox, oy);
            __half2 h1v = __floats2half2_rn(oz, ow);
            uint32_t u0 = *reinterpret_cast<uint32_t*>(&h0);
            uint32_t u1 = *reinterpret_cast<uint32_t*>(&h1v);
            pk = ((ull)u1 << 32) | u0;
        }
        int off = r * 128 + xcol;
        off ^= (off >> 3) & 0x70;
        *reinterpret_cast<ull*>(sX + xsub * SUBB + off) = pk;
    }
    __syncthreads();

    // ---- Phase B: GEMM2 on ALL 16 warps ----
    // warp w: rows (w&7)*16 .. +15, N-half (w>>3) (32 cols each).
    {
        const uint32_t sX32 = smem_u32(sX);
        const uint32_t sW32 = smem_u32(sW);

        const int arow = (lane & 7) + ((lane & 8) ? 8 : 0);
        const int cgb  = (lane >> 4) & 1;
        const int xorv = (lane & 7) << 4;
        const int R  = (wid & 7) * 16;
        const int nh = wid >> 3;                 // 0 or 1

        float acc[4][4];
#pragma unroll
        for (int nt = 0; nt < 4; nt++)
#pragma unroll
            for (int q = 0; q < 4; q++) acc[nt][q] = 0.f;

#pragma unroll
        for (int ks = 0; ks < 8; ks++) {
            uint32_t a[4];
            const int subA = ks >> 2;
            const int grpA = (ks & 3) * 2 + cgb;
            int offA = (R + arow) * 128 + ((grpA * 16) ^ xorv);
            ldsm_x4(a[0], a[1], a[2], a[3], sX32 + subA * SUBB + offA);
#pragma unroll
            for (int jp = 0; jp < 2; jp++) {
                const int jpg = nh * 2 + jp;
                uint32_t b0, b1, b2, b3;
                const int grpB = jpg * 2 + cgb;
                int offB = (ks * 16 + arow) * 128 + ((grpB * 16) ^ xorv);
                ldsm_x4_t(b0, b1, b2, b3, sW32 + offB);
                mma16816(acc[2 * jp + 0], a, b0, b1);
                mma16816(acc[2 * jp + 1], a, b2, b3);
            }
        }

        const int erow = lane >> 2;
        const int ecol = (lane & 3) * 2;
        int gr0 = row0 + R + erow;
        int gr1 = gr0 + 8;
        float dv0 = 1.f, dv1 = 1.f;
        if (gr0 < N_NODES) dv0 = g_dinv[gr0];
        if (gr1 < N_NODES) dv1 = g_dinv[gr1];
#pragma unroll
        for (int nt = 0; nt < 4; nt++) {
            const int colb = nh * 32 + nt * 8 + ecol;
            if (gr0 < N_NODES) {
                __half2 h = __floats2half2_rn(acc[nt][0] * dv0, acc[nt][1] * dv0);
                *reinterpret_cast<__half2*>(g_h2 + (size_t)gr0 * OUT_C + colb) = h;
            }
            if (gr1 < N_NODES) {
                __half2 h = __floats2half2_rn(acc[nt][2] * dv1, acc[nt][3] * dv1);
                *reinterpret_cast<__half2*>(g_h2 + (size_t)gr1 * OUT_C + colb) = h;
            }
        }
    }
}

// ---------------- layer-2 aggregation: half-warp per node, pipelined idx ------
__global__ __launch_bounds__(256)
void k_agg2(float* __restrict__ out, const float* __restrict__ b2) {
    int gw   = (blockIdx.x * 256 + threadIdx.x) >> 5;
    int lane = threadIdx.x & 31;
    int n    = gw * 2 + (lane >> 4);
    int hl   = lane & 15;
    if (n >= N_NODES) return;

    const uint2* Hq = reinterpret_cast<const uint2*>(g_h2);

    float4 a0, a1;
    {
        uint2 r = __ldcg(&Hq[(size_t)n * 16 + hl]);
        float2 f01, f23; UNPACK4(r, f01, f23);
        a0 = make_float4(f01.x, f01.y, f23.x, f23.y);   // self (pre-scaled)
    }
    a1 = make_float4(0.f, 0.f, 0.f, 0.f);

    const int len = __ldg(&g_len[n]);
    const int4* E4 = reinterpret_cast<const int4*>(g_ell + n * CAP);
    const int nfull = len >> 2;

    if (nfull > 0) {
        int4 ia = __ldg(&E4[0]);
#pragma unroll 1
        for (int q = 0; q < nfull; q++) {
            int4 cur = ia;
            if (q + 1 < nfull) ia = __ldg(&E4[q + 1]);
            uint2 r0 = __ldcg(&Hq[(size_t)cur.x * 16 + hl]);
            uint2 r1 = __ldcg(&Hq[(size_t)cur.y * 16 + hl]);
            uint2 r2 = __ldcg(&Hq[(size_t)cur.z * 16 + hl]);
            uint2 r3 = __ldcg(&Hq[(size_t)cur.w * 16 + hl]);
            float2 f01, f23;
            UNPACK4(r0, f01, f23);
            a0.x += f01.x; a0.y += f01.y; a0.z += f23.x; a0.w += f23.y;
            UNPACK4(r1, f01, f23);
            a1.x += f01.x; a1.y += f01.y; a1.z += f23.x; a1.w += f23.y;
            UNPACK4(r2, f01, f23);
            a0.x += f01.x; a0.y += f01.y; a0.z += f23.x; a0.w += f23.y;
            UNPACK4(r3, f01, f23);
            a1.x += f01.x; a1.y += f01.y; a1.z += f23.x; a1.w += f23.y;
        }
    }
    for (int f = nfull << 2; f < len; f++) {
        int s = __ldg(&g_ell[n * CAP + f]);
        uint2 r = __ldcg(&Hq[(size_t)s * 16 + hl]);
        float2 f01, f23; UNPACK4(r, f01, f23);
        a0.x += f01.x; a0.y += f01.y; a0.z += f23.x; a0.w += f23.y;
    }
    a0.x += a1.x; a0.y += a1.y; a0.z += a1.z; a0.w += a1.w;

    float dv = __ldg(&g_dinv[n]);
    float4 b = reinterpret_cast<const float4*>(b2)[hl];
    float4 o;
    o.x = fmaf(a0.x, dv, b.x);
    o.y = fmaf(a0.y, dv, b.y);
    o.z = fmaf(a0.z, dv, b.z);
    o.w = fmaf(a0.w, dv, b.w);
    reinterpret_cast<float4*>(out)[(size_t)n * 16 + hl] = o;
}

// ---------------- launch -------------------------------------------------------
extern "C" void kernel_launch(void* const* d_in, const int* in_sizes, int n_in,
                              void* d_out, int out_size)
{
    const float* x  = (const float*)d_in[0];
    const int*   ei = (const int*)  d_in[1];
    const float* W1 = (const float*)d_in[2];
    const float* b1 = (const float*)d_in[3];
    const float* W2 = (const float*)d_in[4];
    const float* b2 = (const float*)d_in[5];
    float* out = (float*)d_out;

    const int* srcp = ei;             // edge_index[0]
    const int* dstp = ei + N_EDGES;   // edge_index[1]

    __half* h1;
    cudaGetSymbolAddress((void**)&h1, g_h1);

    const int SM1 = 2 * 16384 + 2 * 16384;   // gemm1: A 32KB + W 32KB
    const int SMF = 2 * 16384 + 1 * 16384;   // fused: x2 32KB + W2 16KB

    static cudaStream_t s_aux = nullptr;
    static cudaEvent_t  e_fork = nullptr, e_join = nullptr;
    if (s_aux == nullptr) {
        cudaStreamCreateWithFlags(&s_aux, cudaStreamNonBlocking);
        cudaEventCreateWithFlags(&e_fork, cudaEventDisableTiming);
        cudaEventCreateWithFlags(&e_join, cudaEventDisableTiming);
        cudaFuncSetAttribute(k_gemm_mma<HID_C, false>,
                             cudaFuncAttributeMaxDynamicSharedMemorySize, SM1);
        cudaFuncSetAttribute(k_agg1_gemm2,
                             cudaFuncAttributeMaxDynamicSharedMemorySize, SMF);
    }

    const int tile_blocks = (N_NODES + 127) / 128;   // 391
    const int QTOT = N_EDGES / 4;                    // 200000 int4 quads
    const int QHALF = QTOT / 2;                      // 100000

    // fork point at the start of the call (main stream)
    cudaEventRecord(e_fork, 0);
    cudaStreamWaitEvent(s_aux, e_fork, 0);

    // ---- aux: GEMM1, then second half of the ELL place ----
    k_gemm_mma<HID_C, false><<<tile_blocks, 128, SM1, s_aux>>>(x, W1, h1);
    k_place_ell<<<(QTOT - QHALF + 255) / 256, 256, 0, s_aux>>>(srcp, dstp, QHALF, QTOT);
    cudaEventRecord(e_join, s_aux);

    // ---- main: first half of the ELL place ----
    k_place_ell<<<(QHALF + 255) / 256, 256>>>(srcp, dstp, 0, QHALF);

    // join both halves (and h1), then dinv + fused
    cudaStreamWaitEvent(0, e_join, 0);
    k_dinv<<<(N_NODES + 255) / 256, 256>>>();
    k_agg1_gemm2<<<tile_blocks, 512, SMF>>>(b1, W2);

    // ---- layer-2 aggregation ----
    k_agg2<<<((N_NODES + 1) / 2 * 32 + 255) / 256, 256>>>(out, b2);
}